// round 1
// baseline (speedup 1.0000x reference)
#include <cuda_runtime.h>

// Problem constants
constexpr int DIMC = 64;                 // channels per branch
constexpr int D_ = 64, H_ = 128, W_ = 128;
constexpr int HW_ = H_ * W_;             // 16384
constexpr size_t NSP = (size_t)D_ * HW_; // 1048576 spatial positions
constexpr int KTOT = 3 * DIMC;           // 192 cat channels
constexpr float EPS_ = 1e-5f;
constexpr float SLOPE_ = 0.01f;

// Scratch: pre-norm branch outputs laid out [k = branch*64 + c][spatial] (768 MB)
__device__ float g_scr[(size_t)KTOT * NSP];
// Reduction accumulators / folded norm params
__device__ float g_sum[KTOT];
__device__ float g_sq[KTOT];
__device__ float g_scale[KTOT];
__device__ float g_bias[KTOT];
__device__ float g_osum[DIMC];
__device__ float g_osq[DIMC];
__device__ float g_oscale[DIMC];
__device__ float g_obias[DIMC];

__device__ __forceinline__ float warp_red(float v) {
    #pragma unroll
    for (int o = 16; o > 0; o >>= 1) v += __shfl_down_sync(0xffffffffu, v, o);
    return v;
}

__global__ void k_zero() {
    int t = threadIdx.x;
    if (t < KTOT) { g_sum[t] = 0.f; g_sq[t] = 0.f; }
    if (t < DIMC) { g_osum[t] = 0.f; g_osq[t] = 0.f; }
}

// Fused 3x depthwise conv (+bias) + per-(branch,channel) sum/sumsq partials.
// One block per (d, c). 256 threads sweep the 128x128 plane.
__global__ void __launch_bounds__(256) k_conv(
    const float* __restrict__ x,
    const float* __restrict__ wd, const float* __restrict__ bd,
    const float* __restrict__ wh, const float* __restrict__ bh,
    const float* __restrict__ wv, const float* __restrict__ bw)
{
    const int d = blockIdx.x;
    const int c = blockIdx.y;

    float Wd[9], Wh[9], Wv[9];
    #pragma unroll
    for (int i = 0; i < 9; i++) {
        Wd[i] = wd[c * 9 + i];   // [c][0][0][kh][kw]
        Wh[i] = wh[c * 9 + i];   // [c][0][kd][0][kw]
        Wv[i] = wv[c * 9 + i];   // [c][0][kd][kh][0]
    }
    const float bdv = bd[c], bhv = bh[c], bwv = bw[c];

    const float* pc = x + (size_t)c * NSP + (size_t)d * HW_;
    const float* pm = pc - HW_;
    const float* pp = pc + HW_;
    const bool dm = d > 0, dp = d < D_ - 1;

    float* od = g_scr + (size_t)c * NSP + (size_t)d * HW_;
    float* oh = od + (size_t)DIMC * NSP;
    float* ow = oh + (size_t)DIMC * NSP;

    float s0 = 0.f, q0 = 0.f, s1 = 0.f, q1 = 0.f, s2 = 0.f, q2 = 0.f;

    for (int idx = threadIdx.x; idx < HW_; idx += 256) {
        const int h = idx >> 7;
        const int w = idx & (W_ - 1);
        const bool hm = h > 0, hp = h < H_ - 1, wm = w > 0, wp = w < W_ - 1;

        // center d-plane (9 taps)
        float c_mm = (hm && wm) ? pc[idx - W_ - 1] : 0.f;
        float c_m0 = hm ? pc[idx - W_] : 0.f;
        float c_mp = (hm && wp) ? pc[idx - W_ + 1] : 0.f;
        float c_0m = wm ? pc[idx - 1] : 0.f;
        float c_00 = pc[idx];
        float c_0p = wp ? pc[idx + 1] : 0.f;
        float c_pm = (hp && wm) ? pc[idx + W_ - 1] : 0.f;
        float c_p0 = hp ? pc[idx + W_] : 0.f;
        float c_pp = (hp && wp) ? pc[idx + W_ + 1] : 0.f;
        // d-1 plane (5 taps)
        float m_0m = (dm && wm) ? pm[idx - 1] : 0.f;
        float m_00 = dm ? pm[idx] : 0.f;
        float m_0p = (dm && wp) ? pm[idx + 1] : 0.f;
        float m_m0 = (dm && hm) ? pm[idx - W_] : 0.f;
        float m_p0 = (dm && hp) ? pm[idx + W_] : 0.f;
        // d+1 plane (5 taps)
        float p_0m = (dp && wm) ? pp[idx - 1] : 0.f;
        float p_00 = dp ? pp[idx] : 0.f;
        float p_0p = (dp && wp) ? pp[idx + 1] : 0.f;
        float p_m0 = (dp && hm) ? pp[idx - W_] : 0.f;
        float p_p0 = (dp && hp) ? pp[idx + W_] : 0.f;

        // branch D: 3x3 over (h,w) at fixed d
        float vd = bdv;
        vd = fmaf(Wd[0], c_mm, vd); vd = fmaf(Wd[1], c_m0, vd); vd = fmaf(Wd[2], c_mp, vd);
        vd = fmaf(Wd[3], c_0m, vd); vd = fmaf(Wd[4], c_00, vd); vd = fmaf(Wd[5], c_0p, vd);
        vd = fmaf(Wd[6], c_pm, vd); vd = fmaf(Wd[7], c_p0, vd); vd = fmaf(Wd[8], c_pp, vd);
        // branch H: 3x3 over (d,w) at fixed h
        float vh = bhv;
        vh = fmaf(Wh[0], m_0m, vh); vh = fmaf(Wh[1], m_00, vh); vh = fmaf(Wh[2], m_0p, vh);
        vh = fmaf(Wh[3], c_0m, vh); vh = fmaf(Wh[4], c_00, vh); vh = fmaf(Wh[5], c_0p, vh);
        vh = fmaf(Wh[6], p_0m, vh); vh = fmaf(Wh[7], p_00, vh); vh = fmaf(Wh[8], p_0p, vh);
        // branch W: 3x3 over (d,h) at fixed w
        float vw = bwv;
        vw = fmaf(Wv[0], m_m0, vw); vw = fmaf(Wv[1], m_00, vw); vw = fmaf(Wv[2], m_p0, vw);
        vw = fmaf(Wv[3], c_m0, vw); vw = fmaf(Wv[4], c_00, vw); vw = fmaf(Wv[5], c_p0, vw);
        vw = fmaf(Wv[6], p_m0, vw); vw = fmaf(Wv[7], p_00, vw); vw = fmaf(Wv[8], p_p0, vw);

        od[idx] = vd; oh[idx] = vh; ow[idx] = vw;
        s0 += vd; q0 = fmaf(vd, vd, q0);
        s1 += vh; q1 = fmaf(vh, vh, q1);
        s2 += vw; q2 = fmaf(vw, vw, q2);
    }

    s0 = warp_red(s0); q0 = warp_red(q0);
    s1 = warp_red(s1); q1 = warp_red(q1);
    s2 = warp_red(s2); q2 = warp_red(q2);
    if ((threadIdx.x & 31) == 0) {
        atomicAdd(&g_sum[c], s0);             atomicAdd(&g_sq[c], q0);
        atomicAdd(&g_sum[DIMC + c], s1);      atomicAdd(&g_sq[DIMC + c], q1);
        atomicAdd(&g_sum[2 * DIMC + c], s2);  atomicAdd(&g_sq[2 * DIMC + c], q2);
    }
}

// Fold InstanceNorm into per-k affine: g = v*scale + bias
__global__ void k_stats() {
    int k = threadIdx.x;
    if (k >= KTOT) return;
    const float n = (float)NSP;
    float mean = g_sum[k] / n;
    float var = g_sq[k] / n - mean * mean;
    float sc = rsqrtf(var + EPS_);
    g_scale[k] = sc;
    g_bias[k] = -mean * sc;
}

// Pointwise 192->64 "GEMM" with on-the-fly norm+LeakyReLU of the cat inputs.
// Each thread owns one spatial position and all 64 outputs in registers.
__global__ void __launch_bounds__(256) k_pw(const float* __restrict__ wpw,
                                            const float* __restrict__ bpw,
                                            float* __restrict__ out)
{
    __shared__ float ws[KTOT * DIMC];  // 48 KB, [k][o]
    for (int i = threadIdx.x; i < KTOT * DIMC; i += 256) {
        int k = i >> 6, o = i & 63;
        ws[i] = wpw[o * KTOT + k];     // transpose to k-major
    }
    __syncthreads();

    const size_t pos = (size_t)blockIdx.x * 256 + threadIdx.x;
    const float* gp = g_scr + pos;

    float4 acc[16];
    #pragma unroll
    for (int j = 0; j < 16; j++) acc[j] = make_float4(0.f, 0.f, 0.f, 0.f);

    #pragma unroll 2
    for (int k = 0; k < KTOT; k++) {
        float v = __ldg(gp + (size_t)k * NSP);
        v = fmaf(v, g_scale[k], g_bias[k]);
        v = v >= 0.f ? v : SLOPE_ * v;
        const float4* wr = reinterpret_cast<const float4*>(ws + k * DIMC);
        #pragma unroll
        for (int j = 0; j < 16; j++) {
            float4 wv = wr[j];
            acc[j].x = fmaf(v, wv.x, acc[j].x);
            acc[j].y = fmaf(v, wv.y, acc[j].y);
            acc[j].z = fmaf(v, wv.z, acc[j].z);
            acc[j].w = fmaf(v, wv.w, acc[j].w);
        }
    }

    float* op = out + pos;
    #pragma unroll
    for (int j = 0; j < 16; j++) {
        float4 bv = __ldg(reinterpret_cast<const float4*>(bpw) + j);
        op[(size_t)(4 * j + 0) * NSP] = acc[j].x + bv.x;
        op[(size_t)(4 * j + 1) * NSP] = acc[j].y + bv.y;
        op[(size_t)(4 * j + 2) * NSP] = acc[j].z + bv.z;
        op[(size_t)(4 * j + 3) * NSP] = acc[j].w + bv.w;
    }
}

// Per-output-channel sum/sumsq over the pre-norm output
__global__ void __launch_bounds__(256) k_ostats(const float* __restrict__ out) {
    const int d = blockIdx.x;
    const int c = blockIdx.y;
    const float* p = out + (size_t)c * NSP + (size_t)d * HW_;
    float s = 0.f, q = 0.f;
    for (int idx = threadIdx.x; idx < HW_; idx += 256) {
        float v = p[idx];
        s += v;
        q = fmaf(v, v, q);
    }
    s = warp_red(s); q = warp_red(q);
    if ((threadIdx.x & 31) == 0) {
        atomicAdd(&g_osum[c], s);
        atomicAdd(&g_osq[c], q);
    }
}

__global__ void k_ofin() {
    int c = threadIdx.x;
    if (c >= DIMC) return;
    const float n = (float)NSP;
    float mean = g_osum[c] / n;
    float var = g_osq[c] / n - mean * mean;
    float sc = rsqrtf(var + EPS_);
    g_oscale[c] = sc;
    g_obias[c] = -mean * sc;
}

// In-place output norm + LeakyReLU
__global__ void __launch_bounds__(256) k_onorm(float* __restrict__ out) {
    const int c = blockIdx.y;
    const size_t pos = (size_t)blockIdx.x * 256 + threadIdx.x;
    const size_t i = (size_t)c * NSP + pos;
    float v = out[i];
    v = fmaf(v, g_oscale[c], g_obias[c]);
    v = v >= 0.f ? v : SLOPE_ * v;
    out[i] = v;
}

extern "C" void kernel_launch(void* const* d_in, const int* in_sizes, int n_in,
                              void* d_out, int out_size) {
    const float* x   = (const float*)d_in[0];
    const float* wd  = (const float*)d_in[1];
    const float* bd  = (const float*)d_in[2];
    const float* wh  = (const float*)d_in[3];
    const float* bh  = (const float*)d_in[4];
    const float* wv  = (const float*)d_in[5];
    const float* bw  = (const float*)d_in[6];
    const float* wpw = (const float*)d_in[7];
    const float* bpw = (const float*)d_in[8];
    float* out = (float*)d_out;

    k_zero<<<1, 256>>>();
    dim3 gconv(D_, DIMC);
    k_conv<<<gconv, 256>>>(x, wd, bd, wh, bh, wv, bw);
    k_stats<<<1, KTOT>>>();
    k_pw<<<(unsigned)(NSP / 256), 256>>>(wpw, bpw, out);
    dim3 gos(D_, DIMC);
    k_ostats<<<gos, 256>>>(out);
    k_ofin<<<1, DIMC>>>();
    dim3 gon((unsigned)(NSP / 256), DIMC);
    k_onorm<<<gon, 256>>>(out);
}

// round 2
// speedup vs baseline: 1.5167x; 1.5167x over previous
#include <cuda_runtime.h>

constexpr int DIMC = 64;
constexpr int D_ = 64, H_ = 128, W_ = 128;
constexpr int HW_ = H_ * W_;
constexpr size_t NSP = (size_t)D_ * HW_;
constexpr int KTOT = 3 * DIMC;
constexpr float EPS_ = 1e-5f;
constexpr float SLOPE_ = 0.01f;

__device__ float g_scr[(size_t)KTOT * NSP];
__device__ float g_sum[KTOT];
__device__ float g_sq[KTOT];
__device__ float g_scale[KTOT];
__device__ float g_bias[KTOT];
__device__ float g_osum[DIMC];
__device__ float g_osq[DIMC];
__device__ float g_oscale[DIMC];
__device__ float g_obias[DIMC];

__device__ __forceinline__ float warp_red(float v) {
    #pragma unroll
    for (int o = 16; o > 0; o >>= 1) v += __shfl_down_sync(0xffffffffu, v, o);
    return v;
}

__device__ __forceinline__ unsigned long long dup_f(float v) {
    unsigned long long r;
    asm("mov.b64 %0, {%1, %1};" : "=l"(r) : "f"(v));
    return r;
}
__device__ __forceinline__ void unpack2(unsigned long long v, float& lo, float& hi) {
    asm("mov.b64 {%0, %1}, %2;" : "=f"(lo), "=f"(hi) : "l"(v));
}
#define FMA2(a, v, w) asm("fma.rn.f32x2 %0, %1, %2, %0;" : "+l"(a) : "l"(v), "l"(w))

__global__ void k_zero() {
    int t = threadIdx.x;
    if (t < KTOT) { g_sum[t] = 0.f; g_sq[t] = 0.f; }
    if (t < DIMC) { g_osum[t] = 0.f; g_osq[t] = 0.f; }
}

// Fused 3-branch depthwise conv (+bias) + per-(branch,channel) stats.
// One block per (d, c); threads sweep 4-wide chunks of the 128x128 plane.
__global__ void __launch_bounds__(256) k_conv(
    const float* __restrict__ x,
    const float* __restrict__ wd, const float* __restrict__ bd,
    const float* __restrict__ wh, const float* __restrict__ bh,
    const float* __restrict__ wv, const float* __restrict__ bw)
{
    const int d = blockIdx.x;
    const int c = blockIdx.y;

    float Wd[9], Wh[9], Wv[9];
    #pragma unroll
    for (int i = 0; i < 9; i++) {
        Wd[i] = wd[c * 9 + i];
        Wh[i] = wh[c * 9 + i];
        Wv[i] = wv[c * 9 + i];
    }
    const float bdv = bd[c], bhv = bh[c], bwv = bw[c];

    const float* pc = x + (size_t)c * NSP + (size_t)d * HW_;
    const float* pm = pc - HW_;
    const float* pp = pc + HW_;
    const bool dm = d > 0, dp = d < D_ - 1;

    float* od = g_scr + (size_t)c * NSP + (size_t)d * HW_;
    float* oh = od + (size_t)DIMC * NSP;
    float* ow = oh + (size_t)DIMC * NSP;

    float s0 = 0.f, q0 = 0.f, s1 = 0.f, q1 = 0.f, s2 = 0.f, q2 = 0.f;

    for (int it = threadIdx.x; it < (HW_ >> 2); it += 256) {
        const int h = it >> 5;
        const int w4 = (it & 31) << 2;
        const bool hm = h > 0, hp = h < H_ - 1;
        const bool wl = w4 > 0, wr = w4 < W_ - 4;

        float cm[6], cc6[6], cp[6], mm6[6], pp6[6];
        float mhm[4], mhp[4], phm[4], php[4];

        auto ld6 = [&](float* a, const float* row, bool valid) {
            if (valid) {
                float4 f = *reinterpret_cast<const float4*>(row + w4);
                a[1] = f.x; a[2] = f.y; a[3] = f.z; a[4] = f.w;
                a[0] = wl ? row[w4 - 1] : 0.f;
                a[5] = wr ? row[w4 + 4] : 0.f;
            } else {
                a[0] = a[1] = a[2] = a[3] = a[4] = a[5] = 0.f;
            }
        };
        auto ld4 = [&](float* a, const float* row, bool valid) {
            if (valid) {
                float4 f = *reinterpret_cast<const float4*>(row + w4);
                a[0] = f.x; a[1] = f.y; a[2] = f.z; a[3] = f.w;
            } else {
                a[0] = a[1] = a[2] = a[3] = 0.f;
            }
        };

        const float* rc = pc + h * W_;
        ld6(cc6, rc, true);
        ld6(cm, rc - W_, hm);
        ld6(cp, rc + W_, hp);
        const float* rm = pm + h * W_;
        ld6(mm6, rm, dm);
        ld4(mhm, rm - W_, dm && hm);
        ld4(mhp, rm + W_, dm && hp);
        const float* rp = pp + h * W_;
        ld6(pp6, rp, dp);
        ld4(phm, rp - W_, dp && hm);
        ld4(php, rp + W_, dp && hp);

        float rd[4], rh[4], rw[4];
        #pragma unroll
        for (int i = 0; i < 4; i++) {
            float vd = bdv;
            vd = fmaf(Wd[0], cm[i], vd);  vd = fmaf(Wd[1], cm[i+1], vd);  vd = fmaf(Wd[2], cm[i+2], vd);
            vd = fmaf(Wd[3], cc6[i], vd); vd = fmaf(Wd[4], cc6[i+1], vd); vd = fmaf(Wd[5], cc6[i+2], vd);
            vd = fmaf(Wd[6], cp[i], vd);  vd = fmaf(Wd[7], cp[i+1], vd);  vd = fmaf(Wd[8], cp[i+2], vd);

            float vh = bhv;
            vh = fmaf(Wh[0], mm6[i], vh); vh = fmaf(Wh[1], mm6[i+1], vh); vh = fmaf(Wh[2], mm6[i+2], vh);
            vh = fmaf(Wh[3], cc6[i], vh); vh = fmaf(Wh[4], cc6[i+1], vh); vh = fmaf(Wh[5], cc6[i+2], vh);
            vh = fmaf(Wh[6], pp6[i], vh); vh = fmaf(Wh[7], pp6[i+1], vh); vh = fmaf(Wh[8], pp6[i+2], vh);

            float vw = bwv;
            vw = fmaf(Wv[0], mhm[i], vw);   vw = fmaf(Wv[1], mm6[i+1], vw); vw = fmaf(Wv[2], mhp[i], vw);
            vw = fmaf(Wv[3], cm[i+1], vw);  vw = fmaf(Wv[4], cc6[i+1], vw); vw = fmaf(Wv[5], cp[i+1], vw);
            vw = fmaf(Wv[6], phm[i], vw);   vw = fmaf(Wv[7], pp6[i+1], vw); vw = fmaf(Wv[8], php[i], vw);

            rd[i] = vd; rh[i] = vh; rw[i] = vw;
            s0 += vd; q0 = fmaf(vd, vd, q0);
            s1 += vh; q1 = fmaf(vh, vh, q1);
            s2 += vw; q2 = fmaf(vw, vw, q2);
        }

        const int idx = h * W_ + w4;
        *reinterpret_cast<float4*>(od + idx) = make_float4(rd[0], rd[1], rd[2], rd[3]);
        *reinterpret_cast<float4*>(oh + idx) = make_float4(rh[0], rh[1], rh[2], rh[3]);
        *reinterpret_cast<float4*>(ow + idx) = make_float4(rw[0], rw[1], rw[2], rw[3]);
    }

    s0 = warp_red(s0); q0 = warp_red(q0);
    s1 = warp_red(s1); q1 = warp_red(q1);
    s2 = warp_red(s2); q2 = warp_red(q2);
    if ((threadIdx.x & 31) == 0) {
        atomicAdd(&g_sum[c], s0);             atomicAdd(&g_sq[c], q0);
        atomicAdd(&g_sum[DIMC + c], s1);      atomicAdd(&g_sq[DIMC + c], q1);
        atomicAdd(&g_sum[2 * DIMC + c], s2);  atomicAdd(&g_sq[2 * DIMC + c], q2);
    }
}

__global__ void k_stats() {
    int k = threadIdx.x;
    if (k >= KTOT) return;
    const float n = (float)NSP;
    float mean = g_sum[k] / n;
    float var = g_sq[k] / n - mean * mean;
    float sc = rsqrtf(var + EPS_);
    g_scale[k] = sc;
    g_bias[k] = -mean * sc;
}

// Pointwise 192->64 GEMM with on-the-fly norm+LeakyReLU.
// Thread: 4 consecutive positions x 32 outputs (one half).
// Grid: (2 halves, NSP/1024 position blocks) so the two halves share L2.
__global__ void __launch_bounds__(256, 1) k_pw(const float* __restrict__ wpw,
                                               const float* __restrict__ bpw,
                                               float* __restrict__ out)
{
    __shared__ __align__(16) float ws[KTOT * 32];  // [k][32 outputs of this half]
    __shared__ float2 sb[KTOT];
    const int obase = blockIdx.x * 32;

    for (int i = threadIdx.x; i < KTOT * 32; i += 256) {
        int k = i >> 5, o = i & 31;
        ws[i] = wpw[(size_t)(obase + o) * KTOT + k];
    }
    for (int k = threadIdx.x; k < KTOT; k += 256)
        sb[k] = make_float2(g_scale[k], g_bias[k]);
    __syncthreads();

    const size_t pos = ((size_t)blockIdx.y * 256 + threadIdx.x) * 4;
    const float* gp = g_scr + pos;

    unsigned long long acc[16][4];
    const unsigned long long z = dup_f(0.f);
    #pragma unroll
    for (int j = 0; j < 16; j++)
        #pragma unroll
        for (int p = 0; p < 4; p++) acc[j][p] = z;

    auto do_k = [&](int k, float4 v4) {
        float2 s = sb[k];
        float v[4] = {v4.x, v4.y, v4.z, v4.w};
        unsigned long long vv[4];
        #pragma unroll
        for (int p = 0; p < 4; p++) {
            float t = fmaf(v[p], s.x, s.y);
            t = t >= 0.f ? t : SLOPE_ * t;
            vv[p] = dup_f(t);
        }
        const ulonglong2* wr = reinterpret_cast<const ulonglong2*>(ws + k * 32);
        #pragma unroll
        for (int j = 0; j < 8; j++) {
            ulonglong2 w2 = wr[j];
            #pragma unroll
            for (int p = 0; p < 4; p++) FMA2(acc[2 * j][p], vv[p], w2.x);
            #pragma unroll
            for (int p = 0; p < 4; p++) FMA2(acc[2 * j + 1][p], vv[p], w2.y);
        }
    };

    // depth-2 (pairwise) prefetch over k
    float4 va = *reinterpret_cast<const float4*>(gp);
    float4 vb = *reinterpret_cast<const float4*>(gp + NSP);
    for (int k = 0; k < KTOT; k += 2) {
        float4 na, nb;
        if (k + 2 < KTOT) {
            na = *reinterpret_cast<const float4*>(gp + (size_t)(k + 2) * NSP);
            nb = *reinterpret_cast<const float4*>(gp + (size_t)(k + 3) * NSP);
        }
        do_k(k, va);
        do_k(k + 1, vb);
        va = na; vb = nb;
    }

    #pragma unroll
    for (int j = 0; j < 16; j++) {
        const int o0 = obase + 2 * j, o1 = o0 + 1;
        const float b0 = __ldg(bpw + o0), b1 = __ldg(bpw + o1);
        float lo[4], hi[4];
        #pragma unroll
        for (int p = 0; p < 4; p++) unpack2(acc[j][p], lo[p], hi[p]);
        *reinterpret_cast<float4*>(out + (size_t)o0 * NSP + pos) =
            make_float4(lo[0] + b0, lo[1] + b0, lo[2] + b0, lo[3] + b0);
        *reinterpret_cast<float4*>(out + (size_t)o1 * NSP + pos) =
            make_float4(hi[0] + b1, hi[1] + b1, hi[2] + b1, hi[3] + b1);
    }
}

__global__ void __launch_bounds__(256) k_ostats(const float* __restrict__ out) {
    const int d = blockIdx.x;
    const int c = blockIdx.y;
    const float4* p = reinterpret_cast<const float4*>(out + (size_t)c * NSP + (size_t)d * HW_);
    float s = 0.f, q = 0.f;
    for (int i = threadIdx.x; i < (HW_ >> 2); i += 256) {
        float4 v = p[i];
        s += v.x + v.y + v.z + v.w;
        q = fmaf(v.x, v.x, q); q = fmaf(v.y, v.y, q);
        q = fmaf(v.z, v.z, q); q = fmaf(v.w, v.w, q);
    }
    s = warp_red(s); q = warp_red(q);
    if ((threadIdx.x & 31) == 0) {
        atomicAdd(&g_osum[c], s);
        atomicAdd(&g_osq[c], q);
    }
}

__global__ void k_ofin() {
    int c = threadIdx.x;
    if (c >= DIMC) return;
    const float n = (float)NSP;
    float mean = g_osum[c] / n;
    float var = g_osq[c] / n - mean * mean;
    float sc = rsqrtf(var + EPS_);
    g_oscale[c] = sc;
    g_obias[c] = -mean * sc;
}

__global__ void __launch_bounds__(256) k_onorm(float* __restrict__ out) {
    const int c = blockIdx.y;
    const size_t pos = ((size_t)blockIdx.x * 256 + threadIdx.x) * 4;
    float4* p = reinterpret_cast<float4*>(out + (size_t)c * NSP + pos);
    float4 v = *p;
    const float sc = g_oscale[c], bi = g_obias[c];
    v.x = fmaf(v.x, sc, bi); v.x = v.x >= 0.f ? v.x : SLOPE_ * v.x;
    v.y = fmaf(v.y, sc, bi); v.y = v.y >= 0.f ? v.y : SLOPE_ * v.y;
    v.z = fmaf(v.z, sc, bi); v.z = v.z >= 0.f ? v.z : SLOPE_ * v.z;
    v.w = fmaf(v.w, sc, bi); v.w = v.w >= 0.f ? v.w : SLOPE_ * v.w;
    *p = v;
}

extern "C" void kernel_launch(void* const* d_in, const int* in_sizes, int n_in,
                              void* d_out, int out_size) {
    const float* x   = (const float*)d_in[0];
    const float* wd  = (const float*)d_in[1];
    const float* bd  = (const float*)d_in[2];
    const float* wh  = (const float*)d_in[3];
    const float* bh  = (const float*)d_in[4];
    const float* wv  = (const float*)d_in[5];
    const float* bw  = (const float*)d_in[6];
    const float* wpw = (const float*)d_in[7];
    const float* bpw = (const float*)d_in[8];
    float* out = (float*)d_out;

    k_zero<<<1, 256>>>();
    k_conv<<<dim3(D_, DIMC), 256>>>(x, wd, bd, wh, bh, wv, bw);
    k_stats<<<1, KTOT>>>();
    k_pw<<<dim3(2, (unsigned)(NSP / 1024)), 256>>>(wpw, bpw, out);
    k_ostats<<<dim3(D_, DIMC), 256>>>(out);
    k_ofin<<<1, DIMC>>>();
    k_onorm<<<dim3((unsigned)(NSP / 1024), DIMC), 256>>>(out);
}

// round 3
// speedup vs baseline: 1.9823x; 1.3070x over previous
#include <cuda_runtime.h>
#include <cuda_fp16.h>

constexpr int DIMC = 64;
constexpr int D_ = 64, H_ = 128, W_ = 128;
constexpr int HW_ = H_ * W_;
constexpr size_t NSP = (size_t)D_ * HW_;
constexpr int KTOT = 3 * DIMC;
constexpr float EPS_ = 1e-5f;
constexpr float SLOPE_ = 0.01f;

// fp16 scratch: pre-norm branch outputs [k][spatial] (384 MB)
__device__ __half g_scrh[(size_t)KTOT * NSP];
__device__ float g_sum[KTOT];
__device__ float g_sq[KTOT];
__device__ float g_scale[KTOT];
__device__ float g_bias[KTOT];
__device__ float g_osum[DIMC];
__device__ float g_osq[DIMC];
__device__ float g_oscale[DIMC];
__device__ float g_obias[DIMC];

__device__ __forceinline__ float warp_red(float v) {
    #pragma unroll
    for (int o = 16; o > 0; o >>= 1) v += __shfl_down_sync(0xffffffffu, v, o);
    return v;
}

__device__ __forceinline__ unsigned long long dup_f(float v) {
    unsigned long long r;
    asm("mov.b64 %0, {%1, %1};" : "=l"(r) : "f"(v));
    return r;
}
__device__ __forceinline__ void unpack2(unsigned long long v, float& lo, float& hi) {
    asm("mov.b64 {%0, %1}, %2;" : "=f"(lo), "=f"(hi) : "l"(v));
}
#define FMA2(a, v, w) asm("fma.rn.f32x2 %0, %1, %2, %0;" : "+l"(a) : "l"(v), "l"(w))

__global__ void k_zero() {
    int t = threadIdx.x;
    if (t < KTOT) { g_sum[t] = 0.f; g_sq[t] = 0.f; }
    if (t < DIMC) { g_osum[t] = 0.f; g_osq[t] = 0.f; }
}

// Fused 3-branch depthwise conv (+bias) + fp32 stats, fp16 scratch stores.
__global__ void __launch_bounds__(256) k_conv(
    const float* __restrict__ x,
    const float* __restrict__ wd, const float* __restrict__ bd,
    const float* __restrict__ wh, const float* __restrict__ bh,
    const float* __restrict__ wv, const float* __restrict__ bw)
{
    const int d = blockIdx.x;
    const int c = blockIdx.y;

    float Wd[9], Wh[9], Wv[9];
    #pragma unroll
    for (int i = 0; i < 9; i++) {
        Wd[i] = wd[c * 9 + i];
        Wh[i] = wh[c * 9 + i];
        Wv[i] = wv[c * 9 + i];
    }
    const float bdv = bd[c], bhv = bh[c], bwv = bw[c];

    const float* pc = x + (size_t)c * NSP + (size_t)d * HW_;
    const float* pm = pc - HW_;
    const float* pp = pc + HW_;
    const bool dm = d > 0, dp = d < D_ - 1;

    __half* od = g_scrh + (size_t)c * NSP + (size_t)d * HW_;
    __half* oh = od + (size_t)DIMC * NSP;
    __half* ow = oh + (size_t)DIMC * NSP;

    float s0 = 0.f, q0 = 0.f, s1 = 0.f, q1 = 0.f, s2 = 0.f, q2 = 0.f;

    for (int it = threadIdx.x; it < (HW_ >> 2); it += 256) {
        const int h = it >> 5;
        const int w4 = (it & 31) << 2;
        const bool hm = h > 0, hp = h < H_ - 1;
        const bool wl = w4 > 0, wr = w4 < W_ - 4;

        float cm[6], cc6[6], cp[6], mm6[6], pp6[6];
        float mhm[4], mhp[4], phm[4], php[4];

        auto ld6 = [&](float* a, const float* row, bool valid) {
            if (valid) {
                float4 f = *reinterpret_cast<const float4*>(row + w4);
                a[1] = f.x; a[2] = f.y; a[3] = f.z; a[4] = f.w;
                a[0] = wl ? row[w4 - 1] : 0.f;
                a[5] = wr ? row[w4 + 4] : 0.f;
            } else {
                a[0] = a[1] = a[2] = a[3] = a[4] = a[5] = 0.f;
            }
        };
        auto ld4 = [&](float* a, const float* row, bool valid) {
            if (valid) {
                float4 f = *reinterpret_cast<const float4*>(row + w4);
                a[0] = f.x; a[1] = f.y; a[2] = f.z; a[3] = f.w;
            } else {
                a[0] = a[1] = a[2] = a[3] = 0.f;
            }
        };

        const float* rc = pc + h * W_;
        ld6(cc6, rc, true);
        ld6(cm, rc - W_, hm);
        ld6(cp, rc + W_, hp);
        const float* rm = pm + h * W_;
        ld6(mm6, rm, dm);
        ld4(mhm, rm - W_, dm && hm);
        ld4(mhp, rm + W_, dm && hp);
        const float* rp = pp + h * W_;
        ld6(pp6, rp, dp);
        ld4(phm, rp - W_, dp && hm);
        ld4(php, rp + W_, dp && hp);

        float rd[4], rh[4], rw[4];
        #pragma unroll
        for (int i = 0; i < 4; i++) {
            float vd = bdv;
            vd = fmaf(Wd[0], cm[i], vd);  vd = fmaf(Wd[1], cm[i+1], vd);  vd = fmaf(Wd[2], cm[i+2], vd);
            vd = fmaf(Wd[3], cc6[i], vd); vd = fmaf(Wd[4], cc6[i+1], vd); vd = fmaf(Wd[5], cc6[i+2], vd);
            vd = fmaf(Wd[6], cp[i], vd);  vd = fmaf(Wd[7], cp[i+1], vd);  vd = fmaf(Wd[8], cp[i+2], vd);

            float vh = bhv;
            vh = fmaf(Wh[0], mm6[i], vh); vh = fmaf(Wh[1], mm6[i+1], vh); vh = fmaf(Wh[2], mm6[i+2], vh);
            vh = fmaf(Wh[3], cc6[i], vh); vh = fmaf(Wh[4], cc6[i+1], vh); vh = fmaf(Wh[5], cc6[i+2], vh);
            vh = fmaf(Wh[6], pp6[i], vh); vh = fmaf(Wh[7], pp6[i+1], vh); vh = fmaf(Wh[8], pp6[i+2], vh);

            float vw = bwv;
            vw = fmaf(Wv[0], mhm[i], vw);   vw = fmaf(Wv[1], mm6[i+1], vw); vw = fmaf(Wv[2], mhp[i], vw);
            vw = fmaf(Wv[3], cm[i+1], vw);  vw = fmaf(Wv[4], cc6[i+1], vw); vw = fmaf(Wv[5], cp[i+1], vw);
            vw = fmaf(Wv[6], phm[i], vw);   vw = fmaf(Wv[7], pp6[i+1], vw); vw = fmaf(Wv[8], php[i], vw);

            rd[i] = vd; rh[i] = vh; rw[i] = vw;
            s0 += vd; q0 = fmaf(vd, vd, q0);
            s1 += vh; q1 = fmaf(vh, vh, q1);
            s2 += vw; q2 = fmaf(vw, vw, q2);
        }

        const int idx = h * W_ + w4;
        __half2 a0 = __floats2half2_rn(rd[0], rd[1]);
        __half2 a1 = __floats2half2_rn(rd[2], rd[3]);
        __half2 b0 = __floats2half2_rn(rh[0], rh[1]);
        __half2 b1 = __floats2half2_rn(rh[2], rh[3]);
        __half2 c0 = __floats2half2_rn(rw[0], rw[1]);
        __half2 c1 = __floats2half2_rn(rw[2], rw[3]);
        *reinterpret_cast<uint2*>(od + idx) =
            make_uint2(*reinterpret_cast<unsigned*>(&a0), *reinterpret_cast<unsigned*>(&a1));
        *reinterpret_cast<uint2*>(oh + idx) =
            make_uint2(*reinterpret_cast<unsigned*>(&b0), *reinterpret_cast<unsigned*>(&b1));
        *reinterpret_cast<uint2*>(ow + idx) =
            make_uint2(*reinterpret_cast<unsigned*>(&c0), *reinterpret_cast<unsigned*>(&c1));
    }

    s0 = warp_red(s0); q0 = warp_red(q0);
    s1 = warp_red(s1); q1 = warp_red(q1);
    s2 = warp_red(s2); q2 = warp_red(q2);
    if ((threadIdx.x & 31) == 0) {
        atomicAdd(&g_sum[c], s0);             atomicAdd(&g_sq[c], q0);
        atomicAdd(&g_sum[DIMC + c], s1);      atomicAdd(&g_sq[DIMC + c], q1);
        atomicAdd(&g_sum[2 * DIMC + c], s2);  atomicAdd(&g_sq[2 * DIMC + c], q2);
    }
}

__global__ void k_stats() {
    int k = threadIdx.x;
    if (k >= KTOT) return;
    const float n = (float)NSP;
    float mean = g_sum[k] / n;
    float var = g_sq[k] / n - mean * mean;
    float sc = rsqrtf(var + EPS_);
    g_scale[k] = sc;
    g_bias[k] = -mean * sc;
}

// Pointwise 192->64 GEMM, on-the-fly norm+LeakyReLU of fp16 scratch.
// Thread: 4 positions x 16 outputs (packed output-pairs). 2 blocks/SM.
// Grid: (4 output quarters, pos blocks) -> quarters share scratch via L2.
// Epilogue fuses per-output-channel sum/sumsq (replaces k_ostats).
__global__ void __launch_bounds__(256, 2) k_pw(const float* __restrict__ wpw,
                                               const float* __restrict__ bpw,
                                               float* __restrict__ out)
{
    __shared__ __align__(16) float ws[KTOT * 16];  // [k][16 outputs of this quarter]
    __shared__ float2 sb[KTOT];
    const int obase = blockIdx.x * 16;

    for (int i = threadIdx.x; i < KTOT * 16; i += 256) {
        int k = i >> 4, o = i & 15;
        ws[i] = wpw[(size_t)(obase + o) * KTOT + k];
    }
    for (int k = threadIdx.x; k < KTOT; k += 256)
        sb[k] = make_float2(g_scale[k], g_bias[k]);
    __syncthreads();

    const size_t pos = ((size_t)blockIdx.y * 256 + threadIdx.x) * 4;
    const __half* gp = g_scrh + pos;

    unsigned long long acc[8][4];
    const unsigned long long z = dup_f(0.f);
    #pragma unroll
    for (int j = 0; j < 8; j++)
        #pragma unroll
        for (int p = 0; p < 4; p++) acc[j][p] = z;

    auto do_k = [&](int k, uint2 raw) {
        float2 s = sb[k];
        __half2 h0 = *reinterpret_cast<__half2*>(&raw.x);
        __half2 h1 = *reinterpret_cast<__half2*>(&raw.y);
        float2 f0 = __half22float2(h0);
        float2 f1 = __half22float2(h1);
        float v[4] = {f0.x, f0.y, f1.x, f1.y};
        unsigned long long vv[4];
        #pragma unroll
        for (int p = 0; p < 4; p++) {
            float t = fmaf(v[p], s.x, s.y);
            t = t >= 0.f ? t : SLOPE_ * t;
            vv[p] = dup_f(t);
        }
        const ulonglong2* wr = reinterpret_cast<const ulonglong2*>(ws + k * 16);
        #pragma unroll
        for (int j = 0; j < 4; j++) {
            ulonglong2 w2 = wr[j];
            #pragma unroll
            for (int p = 0; p < 4; p++) FMA2(acc[2 * j][p], vv[p], w2.x);
            #pragma unroll
            for (int p = 0; p < 4; p++) FMA2(acc[2 * j + 1][p], vv[p], w2.y);
        }
    };

    uint2 va = *reinterpret_cast<const uint2*>(gp);
    uint2 vb = *reinterpret_cast<const uint2*>(gp + NSP);
    for (int k = 0; k < KTOT; k += 2) {
        uint2 na, nb;
        if (k + 2 < KTOT) {
            na = *reinterpret_cast<const uint2*>(gp + (size_t)(k + 2) * NSP);
            nb = *reinterpret_cast<const uint2*>(gp + (size_t)(k + 3) * NSP);
        }
        do_k(k, va);
        do_k(k + 1, vb);
        va = na; vb = nb;
    }

    // Epilogue: add bias, store, and accumulate per-output sum/sumsq.
    float s_loc[16], q_loc[16];
    #pragma unroll
    for (int j = 0; j < 8; j++) {
        const int o0 = obase + 2 * j, o1 = o0 + 1;
        const float b0 = __ldg(bpw + o0), b1 = __ldg(bpw + o1);
        float lo[4], hi[4];
        #pragma unroll
        for (int p = 0; p < 4; p++) {
            unpack2(acc[j][p], lo[p], hi[p]);
            lo[p] += b0; hi[p] += b1;
        }
        *reinterpret_cast<float4*>(out + (size_t)o0 * NSP + pos) =
            make_float4(lo[0], lo[1], lo[2], lo[3]);
        *reinterpret_cast<float4*>(out + (size_t)o1 * NSP + pos) =
            make_float4(hi[0], hi[1], hi[2], hi[3]);
        float s0 = 0.f, q0 = 0.f, s1 = 0.f, q1 = 0.f;
        #pragma unroll
        for (int p = 0; p < 4; p++) {
            s0 += lo[p]; q0 = fmaf(lo[p], lo[p], q0);
            s1 += hi[p]; q1 = fmaf(hi[p], hi[p], q1);
        }
        s_loc[2 * j] = s0; q_loc[2 * j] = q0;
        s_loc[2 * j + 1] = s1; q_loc[2 * j + 1] = q1;
    }
    #pragma unroll
    for (int t = 0; t < 16; t++) {
        s_loc[t] = warp_red(s_loc[t]);
        q_loc[t] = warp_red(q_loc[t]);
    }
    if ((threadIdx.x & 31) == 0) {
        #pragma unroll
        for (int t = 0; t < 16; t++) {
            atomicAdd(&g_osum[obase + t], s_loc[t]);
            atomicAdd(&g_osq[obase + t], q_loc[t]);
        }
    }
}

__global__ void k_ofin() {
    int c = threadIdx.x;
    if (c >= DIMC) return;
    const float n = (float)NSP;
    float mean = g_osum[c] / n;
    float var = g_osq[c] / n - mean * mean;
    float sc = rsqrtf(var + EPS_);
    g_oscale[c] = sc;
    g_obias[c] = -mean * sc;
}

__global__ void __launch_bounds__(256) k_onorm(float* __restrict__ out) {
    const int c = blockIdx.y;
    const size_t pos = ((size_t)blockIdx.x * 256 + threadIdx.x) * 4;
    float4* p = reinterpret_cast<float4*>(out + (size_t)c * NSP + pos);
    float4 v = *p;
    const float sc = g_oscale[c], bi = g_obias[c];
    v.x = fmaf(v.x, sc, bi); v.x = v.x >= 0.f ? v.x : SLOPE_ * v.x;
    v.y = fmaf(v.y, sc, bi); v.y = v.y >= 0.f ? v.y : SLOPE_ * v.y;
    v.z = fmaf(v.z, sc, bi); v.z = v.z >= 0.f ? v.z : SLOPE_ * v.z;
    v.w = fmaf(v.w, sc, bi); v.w = v.w >= 0.f ? v.w : SLOPE_ * v.w;
    *p = v;
}

extern "C" void kernel_launch(void* const* d_in, const int* in_sizes, int n_in,
                              void* d_out, int out_size) {
    const float* x   = (const float*)d_in[0];
    const float* wd  = (const float*)d_in[1];
    const float* bd  = (const float*)d_in[2];
    const float* wh  = (const float*)d_in[3];
    const float* bh  = (const float*)d_in[4];
    const float* wv  = (const float*)d_in[5];
    const float* bw  = (const float*)d_in[6];
    const float* wpw = (const float*)d_in[7];
    const float* bpw = (const float*)d_in[8];
    float* out = (float*)d_out;

    k_zero<<<1, 256>>>();
    k_conv<<<dim3(D_, DIMC), 256>>>(x, wd, bd, wh, bh, wv, bw);
    k_stats<<<1, KTOT>>>();
    k_pw<<<dim3(4, (unsigned)(NSP / 1024)), 256>>>(wpw, bpw, out);
    k_ofin<<<1, DIMC>>>();
    k_onorm<<<dim3((unsigned)(NSP / 1024), DIMC), 256>>>(out);
}

// round 6
// speedup vs baseline: 2.9007x; 1.4633x over previous
#include <cuda_runtime.h>
#include <cuda_fp16.h>
#include <cstdint>

constexpr int DIMC = 64;
constexpr int D_ = 64, H_ = 128, W_ = 128;
constexpr int HW_ = H_ * W_;
constexpr size_t NSP = (size_t)D_ * HW_;
constexpr int KTOT = 3 * DIMC;
constexpr float EPS_ = 1e-5f;
constexpr float SLOPE_ = 0.01f;

// fp16 scratch: pre-norm branch outputs [k][spatial] (384 MB)
__device__ __align__(16) __half g_scrh[(size_t)KTOT * NSP];
// fp16 pointwise weights [k][n] (192 x 64)
__device__ __align__(16) __half g_wh[KTOT * 64];
__device__ float g_sum[KTOT];
__device__ float g_sq[KTOT];
__device__ float g_scale[KTOT];
__device__ float g_bias[KTOT];
__device__ float g_osum[DIMC];
__device__ float g_osq[DIMC];
__device__ float g_oscale[DIMC];
__device__ float g_obias[DIMC];

__device__ __forceinline__ float warp_red(float v) {
    #pragma unroll
    for (int o = 16; o > 0; o >>= 1) v += __shfl_down_sync(0xffffffffu, v, o);
    return v;
}

__device__ __forceinline__ uint32_t smem_to_u32(const void* p) {
    uint32_t a;
    asm("{ .reg .u64 t; cvta.to.shared.u64 t, %1; cvt.u32.u64 %0, t; }" : "=r"(a) : "l"(p));
    return a;
}

// ldmatrix x4 transposed (b16): 4 8x8 matrices, rows given per-lane.
__device__ __forceinline__ void ldmx4t(uint32_t* r, uint32_t addr) {
    asm volatile("ldmatrix.sync.aligned.m8n8.x4.trans.shared.b16 {%0,%1,%2,%3}, [%4];"
                 : "=r"(r[0]), "=r"(r[1]), "=r"(r[2]), "=r"(r[3]) : "r"(addr));
}

__device__ __forceinline__ void mma16816(float* d, const uint32_t* a, uint32_t b0, uint32_t b1) {
    asm volatile("mma.sync.aligned.m16n8k16.row.col.f32.f16.f16.f32 "
                 "{%0,%1,%2,%3}, {%4,%5,%6,%7}, {%8,%9}, {%0,%1,%2,%3};"
                 : "+f"(d[0]), "+f"(d[1]), "+f"(d[2]), "+f"(d[3])
                 : "r"(a[0]), "r"(a[1]), "r"(a[2]), "r"(a[3]), "r"(b0), "r"(b1));
}

__global__ void k_zero() {
    int t = threadIdx.x;
    if (t < KTOT) { g_sum[t] = 0.f; g_sq[t] = 0.f; }
    if (t < DIMC) { g_osum[t] = 0.f; g_osq[t] = 0.f; }
}

// Weights fp32 [o][k] -> fp16 [k][n]
__global__ void k_prepB(const float* __restrict__ wpw) {
    for (int idx = threadIdx.x; idx < 64 * KTOT; idx += blockDim.x) {
        int k = idx >> 6, n = idx & 63;
        g_wh[idx] = __float2half(wpw[n * KTOT + k]);
    }
}

// Fused 3-branch depthwise conv (+bias) + fp32 stats, fp16 scratch stores.
__global__ void __launch_bounds__(256) k_conv(
    const float* __restrict__ x,
    const float* __restrict__ wd, const float* __restrict__ bd,
    const float* __restrict__ wh, const float* __restrict__ bh,
    const float* __restrict__ wv, const float* __restrict__ bw)
{
    const int d = blockIdx.x;
    const int c = blockIdx.y;

    float Wd[9], Wh[9], Wv[9];
    #pragma unroll
    for (int i = 0; i < 9; i++) {
        Wd[i] = wd[c * 9 + i];
        Wh[i] = wh[c * 9 + i];
        Wv[i] = wv[c * 9 + i];
    }
    const float bdv = bd[c], bhv = bh[c], bwv = bw[c];

    const float* pc = x + (size_t)c * NSP + (size_t)d * HW_;
    const float* pm = pc - HW_;
    const float* pp = pc + HW_;
    const bool dm = d > 0, dp = d < D_ - 1;

    __half* od = g_scrh + (size_t)c * NSP + (size_t)d * HW_;
    __half* oh = od + (size_t)DIMC * NSP;
    __half* ow = oh + (size_t)DIMC * NSP;

    float s0 = 0.f, q0 = 0.f, s1 = 0.f, q1 = 0.f, s2 = 0.f, q2 = 0.f;

    for (int it = threadIdx.x; it < (HW_ >> 2); it += 256) {
        const int h = it >> 5;
        const int w4 = (it & 31) << 2;
        const bool hm = h > 0, hp = h < H_ - 1;
        const bool wl = w4 > 0, wr = w4 < W_ - 4;

        float cm[6], cc6[6], cp[6], mm6[6], pp6[6];
        float mhm[4], mhp[4], phm[4], php[4];

        auto ld6 = [&](float* a, const float* row, bool valid) {
            if (valid) {
                float4 f = *reinterpret_cast<const float4*>(row + w4);
                a[1] = f.x; a[2] = f.y; a[3] = f.z; a[4] = f.w;
                a[0] = wl ? row[w4 - 1] : 0.f;
                a[5] = wr ? row[w4 + 4] : 0.f;
            } else {
                a[0] = a[1] = a[2] = a[3] = a[4] = a[5] = 0.f;
            }
        };
        auto ld4 = [&](float* a, const float* row, bool valid) {
            if (valid) {
                float4 f = *reinterpret_cast<const float4*>(row + w4);
                a[0] = f.x; a[1] = f.y; a[2] = f.z; a[3] = f.w;
            } else {
                a[0] = a[1] = a[2] = a[3] = 0.f;
            }
        };

        const float* rc = pc + h * W_;
        ld6(cc6, rc, true);
        ld6(cm, rc - W_, hm);
        ld6(cp, rc + W_, hp);
        const float* rm = pm + h * W_;
        ld6(mm6, rm, dm);
        ld4(mhm, rm - W_, dm && hm);
        ld4(mhp, rm + W_, dm && hp);
        const float* rp = pp + h * W_;
        ld6(pp6, rp, dp);
        ld4(phm, rp - W_, dp && hm);
        ld4(php, rp + W_, dp && hp);

        float rd[4], rh[4], rw[4];
        #pragma unroll
        for (int i = 0; i < 4; i++) {
            float vd = bdv;
            vd = fmaf(Wd[0], cm[i], vd);  vd = fmaf(Wd[1], cm[i+1], vd);  vd = fmaf(Wd[2], cm[i+2], vd);
            vd = fmaf(Wd[3], cc6[i], vd); vd = fmaf(Wd[4], cc6[i+1], vd); vd = fmaf(Wd[5], cc6[i+2], vd);
            vd = fmaf(Wd[6], cp[i], vd);  vd = fmaf(Wd[7], cp[i+1], vd);  vd = fmaf(Wd[8], cp[i+2], vd);

            float vh = bhv;
            vh = fmaf(Wh[0], mm6[i], vh); vh = fmaf(Wh[1], mm6[i+1], vh); vh = fmaf(Wh[2], mm6[i+2], vh);
            vh = fmaf(Wh[3], cc6[i], vh); vh = fmaf(Wh[4], cc6[i+1], vh); vh = fmaf(Wh[5], cc6[i+2], vh);
            vh = fmaf(Wh[6], pp6[i], vh); vh = fmaf(Wh[7], pp6[i+1], vh); vh = fmaf(Wh[8], pp6[i+2], vh);

            float vw = bwv;
            vw = fmaf(Wv[0], mhm[i], vw);   vw = fmaf(Wv[1], mm6[i+1], vw); vw = fmaf(Wv[2], mhp[i], vw);
            vw = fmaf(Wv[3], cm[i+1], vw);  vw = fmaf(Wv[4], cc6[i+1], vw); vw = fmaf(Wv[5], cp[i+1], vw);
            vw = fmaf(Wv[6], phm[i], vw);   vw = fmaf(Wv[7], pp6[i+1], vw); vw = fmaf(Wv[8], php[i], vw);

            rd[i] = vd; rh[i] = vh; rw[i] = vw;
            s0 += vd; q0 = fmaf(vd, vd, q0);
            s1 += vh; q1 = fmaf(vh, vh, q1);
            s2 += vw; q2 = fmaf(vw, vw, q2);
        }

        const int idx = h * W_ + w4;
        __half2 a0 = __floats2half2_rn(rd[0], rd[1]);
        __half2 a1 = __floats2half2_rn(rd[2], rd[3]);
        __half2 b0 = __floats2half2_rn(rh[0], rh[1]);
        __half2 b1 = __floats2half2_rn(rh[2], rh[3]);
        __half2 c0 = __floats2half2_rn(rw[0], rw[1]);
        __half2 c1 = __floats2half2_rn(rw[2], rw[3]);
        *reinterpret_cast<uint2*>(od + idx) =
            make_uint2(*reinterpret_cast<unsigned*>(&a0), *reinterpret_cast<unsigned*>(&a1));
        *reinterpret_cast<uint2*>(oh + idx) =
            make_uint2(*reinterpret_cast<unsigned*>(&b0), *reinterpret_cast<unsigned*>(&b1));
        *reinterpret_cast<uint2*>(ow + idx) =
            make_uint2(*reinterpret_cast<unsigned*>(&c0), *reinterpret_cast<unsigned*>(&c1));
    }

    s0 = warp_red(s0); q0 = warp_red(q0);
    s1 = warp_red(s1); q1 = warp_red(q1);
    s2 = warp_red(s2); q2 = warp_red(q2);
    if ((threadIdx.x & 31) == 0) {
        atomicAdd(&g_sum[c], s0);             atomicAdd(&g_sq[c], q0);
        atomicAdd(&g_sum[DIMC + c], s1);      atomicAdd(&g_sq[DIMC + c], q1);
        atomicAdd(&g_sum[2 * DIMC + c], s2);  atomicAdd(&g_sq[2 * DIMC + c], q2);
    }
}

__global__ void k_stats() {
    int k = threadIdx.x;
    if (k >= KTOT) return;
    const float n = (float)NSP;
    float mean = g_sum[k] / n;
    float var = g_sq[k] / n - mean * mean;
    float sc = rsqrtf(var + EPS_);
    g_scale[k] = sc;
    g_bias[k] = -mean * sc;
}

// ---------- mma.sync pointwise GEMM ----------
// CTA: 128 threads (4 warps). M=128 positions, N=64, K=192.
// A in SMEM [k][m], rows padded to 272B; B [k][n], rows padded to 144B.
// ldmatrix.trans for both operands; fused output-channel stats in epilogue.
constexpr int PW_SM_B = 0;                       // 192 * 144 = 27648
constexpr int PW_SM_A = 27648;                   // 192 * 272 = 52224
constexpr int PW_SM_SB = 27648 + 52224;          // 192 float2 = 1536
constexpr int PW_SM_RED = PW_SM_SB + 1536;       // 128 floats = 512
constexpr int PW_SM_TOTAL = PW_SM_RED + 512;     // 81920
constexpr int A_STRIDE = 272;                    // bytes per k-row (128 halves + 8 pad)
constexpr int B_STRIDE = 144;                    // bytes per k-row (64 halves + 8 pad)

__global__ void __launch_bounds__(128) k_pw_mma(float* __restrict__ out) {
    extern __shared__ char smem[];
    const uint32_t sa = smem_to_u32(smem);
    const int tid = threadIdx.x;
    const int wid = tid >> 5;
    const int lid = tid & 31;
    const size_t base = (size_t)blockIdx.x * 128;

    // B: copy 192 rows x 128B into padded rows
    {
        const uint4* src = reinterpret_cast<const uint4*>(g_wh);
        for (int i = tid; i < KTOT * 8; i += 128) {
            int row = i >> 3, part = i & 7;
            *reinterpret_cast<uint4*>(smem + PW_SM_B + row * B_STRIDE + part * 16) = src[i];
        }
    }
    // scale/bias + zero reduction buffer
    float2* sbp = reinterpret_cast<float2*>(smem + PW_SM_SB);
    for (int k = tid; k < KTOT; k += 128) sbp[k] = make_float2(g_scale[k], g_bias[k]);
    reinterpret_cast<float*>(smem + PW_SM_RED)[tid] = 0.f;
    __syncthreads();

    // A fill: idx -> (g = position group of 8, k); coalesced LDG, contiguous STS.128
    #pragma unroll
    for (int it = 0; it < 24; it++) {
        const int idx = it * 128 + tid;
        const int g = idx & 15;
        const int k = idx >> 4;
        uint4 raw = *reinterpret_cast<const uint4*>(g_scrh + (size_t)k * NSP + base + g * 8);
        float2 s = sbp[k];
        const __half2* hp = reinterpret_cast<const __half2*>(&raw);
        uint4 outv;
        uint32_t* ov = reinterpret_cast<uint32_t*>(&outv);
        #pragma unroll
        for (int q = 0; q < 4; q++) {
            float2 f = __half22float2(hp[q]);
            float v0 = fmaf(f.x, s.x, s.y); v0 = fmaxf(v0, SLOPE_ * v0);
            float v1 = fmaf(f.y, s.x, s.y); v1 = fmaxf(v1, SLOPE_ * v1);
            __half2 h = __floats2half2_rn(v0, v1);
            ov[q] = *reinterpret_cast<uint32_t*>(&h);
        }
        *reinterpret_cast<uint4*>(smem + PW_SM_A + k * A_STRIDE + g * 16) = outv;
    }
    __syncthreads();

    // MMA mainloop: warp owns 32 positions (2 m16 tiles) x 64 n (8 n8 tiles)
    float acc[2][8][4];
    #pragma unroll
    for (int mt = 0; mt < 2; mt++)
        #pragma unroll
        for (int nt = 0; nt < 8; nt++)
            #pragma unroll
            for (int e = 0; e < 4; e++) acc[mt][nt][e] = 0.f;

    // A ldmatrix.x4.trans lane addressing: matrices must arrive in order
    //   (m0,k0), (m8,k0), (m0,k8), (m8,k8)  [m-half fastest]
    const int a_k = (lid & 7) | ((lid & 16) >> 1);  // k row within 16-step
    const int a_m = (lid & 8);                       // m offset 0 or 8
    // B lane addressing: matrices in order (k0,n0), (k8,n0), (k0,n8), (k8,n8)
    const int b_k = lid & 15;
    const int b_n = (lid >> 4) * 8;
    const int m0 = wid * 32;

    #pragma unroll
    for (int ks = 0; ks < 12; ks++) {
        const int k0 = ks * 16;
        uint32_t af[2][4];
        #pragma unroll
        for (int mt = 0; mt < 2; mt++) {
            uint32_t addr = sa + PW_SM_A + (k0 + a_k) * A_STRIDE + (m0 + mt * 16 + a_m) * 2;
            ldmx4t(af[mt], addr);
        }
        uint32_t bf[4][4];
        #pragma unroll
        for (int nb = 0; nb < 4; nb++) {
            uint32_t addr = sa + PW_SM_B + (k0 + b_k) * B_STRIDE + (nb * 16 + b_n) * 2;
            ldmx4t(bf[nb], addr);
        }
        #pragma unroll
        for (int mt = 0; mt < 2; mt++)
            #pragma unroll
            for (int nb = 0; nb < 4; nb++) {
                mma16816(acc[mt][2 * nb],     af[mt], bf[nb][0], bf[nb][1]);
                mma16816(acc[mt][2 * nb + 1], af[mt], bf[nb][2], bf[nb][3]);
            }
    }

    // Epilogue: store + fused channel stats
    const int r_lo = (lid >> 2);
    const int c_off = (lid & 3) * 2;
    float sc0[8], qc0[8], sc1[8], qc1[8];
    #pragma unroll
    for (int nt = 0; nt < 8; nt++) { sc0[nt] = qc0[nt] = sc1[nt] = qc1[nt] = 0.f; }

    #pragma unroll
    for (int mt = 0; mt < 2; mt++) {
        const size_t row0 = base + m0 + mt * 16 + r_lo;
        #pragma unroll
        for (int nt = 0; nt < 8; nt++) {
            const int c0 = nt * 8 + c_off;
            float d0 = acc[mt][nt][0], d1 = acc[mt][nt][1];
            float d2 = acc[mt][nt][2], d3 = acc[mt][nt][3];
            out[(size_t)c0 * NSP + row0]           = d0;
            out[(size_t)(c0 + 1) * NSP + row0]     = d1;
            out[(size_t)c0 * NSP + row0 + 8]       = d2;
            out[(size_t)(c0 + 1) * NSP + row0 + 8] = d3;
            sc0[nt] += d0 + d2; qc0[nt] += d0 * d0 + d2 * d2;
            sc1[nt] += d1 + d3; qc1[nt] += d1 * d1 + d3 * d3;
        }
    }
    // reduce over lanes with same (lid&3): xor 4, 8, 16
    #pragma unroll
    for (int o = 4; o <= 16; o <<= 1) {
        #pragma unroll
        for (int nt = 0; nt < 8; nt++) {
            sc0[nt] += __shfl_xor_sync(0xffffffffu, sc0[nt], o);
            qc0[nt] += __shfl_xor_sync(0xffffffffu, qc0[nt], o);
            sc1[nt] += __shfl_xor_sync(0xffffffffu, sc1[nt], o);
            qc1[nt] += __shfl_xor_sync(0xffffffffu, qc1[nt], o);
        }
    }
    float* red = reinterpret_cast<float*>(smem + PW_SM_RED);  // [0:64) sum, [64:128) sq
    if (lid < 4) {
        #pragma unroll
        for (int nt = 0; nt < 8; nt++) {
            const int c0 = nt * 8 + c_off;
            atomicAdd(&red[c0], sc0[nt]);
            atomicAdd(&red[64 + c0], qc0[nt]);
            atomicAdd(&red[c0 + 1], sc1[nt]);
            atomicAdd(&red[64 + c0 + 1], qc1[nt]);
        }
    }
    __syncthreads();
    if (tid < 64) atomicAdd(&g_osum[tid], red[tid]);
    else atomicAdd(&g_osq[tid - 64], red[tid]);
}

__global__ void k_ofin() {
    int c = threadIdx.x;
    if (c >= DIMC) return;
    const float n = (float)NSP;
    float mean = g_osum[c] / n;
    float var = g_osq[c] / n - mean * mean;
    float sc = rsqrtf(var + EPS_);
    g_oscale[c] = sc;
    g_obias[c] = -mean * sc;
}

__global__ void __launch_bounds__(256) k_onorm(float* __restrict__ out) {
    const int c = blockIdx.y;
    const size_t pos = ((size_t)blockIdx.x * 256 + threadIdx.x) * 4;
    float4* p = reinterpret_cast<float4*>(out + (size_t)c * NSP + pos);
    float4 v = *p;
    const float sc = g_oscale[c], bi = g_obias[c];
    v.x = fmaf(v.x, sc, bi); v.x = fmaxf(v.x, SLOPE_ * v.x);
    v.y = fmaf(v.y, sc, bi); v.y = fmaxf(v.y, SLOPE_ * v.y);
    v.z = fmaf(v.z, sc, bi); v.z = fmaxf(v.z, SLOPE_ * v.z);
    v.w = fmaf(v.w, sc, bi); v.w = fmaxf(v.w, SLOPE_ * v.w);
    *p = v;
}

extern "C" void kernel_launch(void* const* d_in, const int* in_sizes, int n_in,
                              void* d_out, int out_size) {
    const float* x   = (const float*)d_in[0];
    const float* wd  = (const float*)d_in[1];
    const float* bd  = (const float*)d_in[2];
    const float* wh  = (const float*)d_in[3];
    const float* bh  = (const float*)d_in[4];
    const float* wv  = (const float*)d_in[5];
    const float* bw  = (const float*)d_in[6];
    const float* wpw = (const float*)d_in[7];
    // d_in[8] = pointwise bias: dropped (cancels exactly in the output InstanceNorm)
    float* out = (float*)d_out;

    cudaFuncSetAttribute(k_pw_mma, cudaFuncAttributeMaxDynamicSharedMemorySize, PW_SM_TOTAL);

    k_zero<<<1, 256>>>();
    k_prepB<<<1, 256>>>(wpw);
    k_conv<<<dim3(D_, DIMC), 256>>>(x, wd, bd, wh, bh, wv, bw);
    k_stats<<<1, KTOT>>>();
    k_pw_mma<<<(unsigned)(NSP / 128), 128, PW_SM_TOTAL>>>(out);
    k_ofin<<<1, DIMC>>>();
    k_onorm<<<dim3((unsigned)(NSP / 1024), DIMC), 256>>>(out);
}

// round 8
// speedup vs baseline: 3.0579x; 1.0542x over previous
#include <cuda_runtime.h>
#include <cuda_fp16.h>
#include <cstdint>

constexpr int DIMC = 64;
constexpr int D_ = 64, H_ = 128, W_ = 128;
constexpr int HW_ = H_ * W_;
constexpr size_t NSP = (size_t)D_ * HW_;
constexpr int KTOT = 3 * DIMC;
constexpr float EPS_ = 1e-5f;
constexpr float SLOPE_ = 0.01f;

// fp16 scratch: pre-norm branch outputs [k][spatial] (384 MB)
__device__ __align__(16) __half g_scrh[(size_t)KTOT * NSP];
// fp16 pre-norm pointwise output [c][spatial] (128 MB)
__device__ __align__(16) __half g_outh[(size_t)DIMC * NSP];
// fp16 pointwise weights [k][n] (192 x 64)
__device__ __align__(16) __half g_wh[KTOT * 64];
__device__ float g_sum[KTOT];
__device__ float g_sq[KTOT];
__device__ float g_scale[KTOT];
__device__ float g_bias[KTOT];
__device__ float g_osum[DIMC];
__device__ float g_osq[DIMC];
__device__ float g_oscale[DIMC];
__device__ float g_obias[DIMC];

__device__ __forceinline__ float warp_red(float v) {
    #pragma unroll
    for (int o = 16; o > 0; o >>= 1) v += __shfl_down_sync(0xffffffffu, v, o);
    return v;
}

__device__ __forceinline__ uint32_t smem_to_u32(const void* p) {
    uint32_t a;
    asm("{ .reg .u64 t; cvta.to.shared.u64 t, %1; cvt.u32.u64 %0, t; }" : "=r"(a) : "l"(p));
    return a;
}

__device__ __forceinline__ void ldmx4t(uint32_t* r, uint32_t addr) {
    asm volatile("ldmatrix.sync.aligned.m8n8.x4.trans.shared.b16 {%0,%1,%2,%3}, [%4];"
                 : "=r"(r[0]), "=r"(r[1]), "=r"(r[2]), "=r"(r[3]) : "r"(addr));
}

__device__ __forceinline__ void mma16816(float* d, const uint32_t* a, uint32_t b0, uint32_t b1) {
    asm volatile("mma.sync.aligned.m16n8k16.row.col.f32.f16.f16.f32 "
                 "{%0,%1,%2,%3}, {%4,%5,%6,%7}, {%8,%9}, {%0,%1,%2,%3};"
                 : "+f"(d[0]), "+f"(d[1]), "+f"(d[2]), "+f"(d[3])
                 : "r"(a[0]), "r"(a[1]), "r"(a[2]), "r"(a[3]), "r"(b0), "r"(b1));
}

// zero accumulators + weights fp32 [o][k] -> fp16 [k][n]
__global__ void k_prep(const float* __restrict__ wpw) {
    int t = threadIdx.x;
    if (t < KTOT) { g_sum[t] = 0.f; g_sq[t] = 0.f; }
    if (t < DIMC) { g_osum[t] = 0.f; g_osq[t] = 0.f; }
    for (int idx = t; idx < 64 * KTOT; idx += 256) {
        int k = idx >> 6, n = idx & 63;
        g_wh[idx] = __float2half(wpw[n * KTOT + k]);
    }
}

// Fused 3-branch depthwise conv (+bias) + fp32 stats, fp16 scratch stores.
__global__ void __launch_bounds__(256) k_conv(
    const float* __restrict__ x,
    const float* __restrict__ wd, const float* __restrict__ bd,
    const float* __restrict__ wh, const float* __restrict__ bh,
    const float* __restrict__ wv, const float* __restrict__ bw)
{
    const int d = blockIdx.x;
    const int c = blockIdx.y;

    float Wd[9], Wh[9], Wv[9];
    #pragma unroll
    for (int i = 0; i < 9; i++) {
        Wd[i] = wd[c * 9 + i];
        Wh[i] = wh[c * 9 + i];
        Wv[i] = wv[c * 9 + i];
    }
    const float bdv = bd[c], bhv = bh[c], bwv = bw[c];

    const float* pc = x + (size_t)c * NSP + (size_t)d * HW_;
    const float* pm = pc - HW_;
    const float* pp = pc + HW_;
    const bool dm = d > 0, dp = d < D_ - 1;
    const bool dint = dm && dp;

    __half* od = g_scrh + (size_t)c * NSP + (size_t)d * HW_;
    __half* oh = od + (size_t)DIMC * NSP;
    __half* ow = oh + (size_t)DIMC * NSP;

    float s0 = 0.f, q0 = 0.f, s1 = 0.f, q1 = 0.f, s2 = 0.f, q2 = 0.f;

    for (int it = threadIdx.x; it < (HW_ >> 2); it += 256) {
        const int h = it >> 5;
        const int w4 = (it & 31) << 2;

        float cm[6], cc6[6], cp[6], mm6[6], pp6[6];
        float mhm[4], mhp[4], phm[4], php[4];

        const float* rc = pc + h * W_;
        const float* rm = pm + h * W_;
        const float* rp = pp + h * W_;

        auto ld6u = [&](float* a, const float* row) {
            float4 f = *reinterpret_cast<const float4*>(row + w4);
            a[1] = f.x; a[2] = f.y; a[3] = f.z; a[4] = f.w;
            a[0] = row[w4 - 1];
            a[5] = row[w4 + 4];
        };
        auto ld4u = [&](float* a, const float* row) {
            float4 f = *reinterpret_cast<const float4*>(row + w4);
            a[0] = f.x; a[1] = f.y; a[2] = f.z; a[3] = f.w;
        };

        if (dint && h > 0 && h < H_ - 1 && w4 > 0 && w4 < W_ - 4) {
            // interior fast path: no predicates
            ld6u(cc6, rc);  ld6u(cm, rc - W_);  ld6u(cp, rc + W_);
            ld6u(mm6, rm);  ld4u(mhm, rm - W_); ld4u(mhp, rm + W_);
            ld6u(pp6, rp);  ld4u(phm, rp - W_); ld4u(php, rp + W_);
        } else {
            const bool hm = h > 0, hp = h < H_ - 1;
            const bool wl = w4 > 0, wr = w4 < W_ - 4;
            auto ld6 = [&](float* a, const float* row, bool valid) {
                if (valid) {
                    float4 f = *reinterpret_cast<const float4*>(row + w4);
                    a[1] = f.x; a[2] = f.y; a[3] = f.z; a[4] = f.w;
                    a[0] = wl ? row[w4 - 1] : 0.f;
                    a[5] = wr ? row[w4 + 4] : 0.f;
                } else {
                    a[0] = a[1] = a[2] = a[3] = a[4] = a[5] = 0.f;
                }
            };
            auto ld4 = [&](float* a, const float* row, bool valid) {
                if (valid) {
                    float4 f = *reinterpret_cast<const float4*>(row + w4);
                    a[0] = f.x; a[1] = f.y; a[2] = f.z; a[3] = f.w;
                } else {
                    a[0] = a[1] = a[2] = a[3] = 0.f;
                }
            };
            ld6(cc6, rc, true);
            ld6(cm, rc - W_, hm);
            ld6(cp, rc + W_, hp);
            ld6(mm6, rm, dm);
            ld4(mhm, rm - W_, dm && hm);
            ld4(mhp, rm + W_, dm && hp);
            ld6(pp6, rp, dp);
            ld4(phm, rp - W_, dp && hm);
            ld4(php, rp + W_, dp && hp);
        }

        float rd[4], rh[4], rw[4];
        #pragma unroll
        for (int i = 0; i < 4; i++) {
            float vd = bdv;
            vd = fmaf(Wd[0], cm[i], vd);  vd = fmaf(Wd[1], cm[i+1], vd);  vd = fmaf(Wd[2], cm[i+2], vd);
            vd = fmaf(Wd[3], cc6[i], vd); vd = fmaf(Wd[4], cc6[i+1], vd); vd = fmaf(Wd[5], cc6[i+2], vd);
            vd = fmaf(Wd[6], cp[i], vd);  vd = fmaf(Wd[7], cp[i+1], vd);  vd = fmaf(Wd[8], cp[i+2], vd);

            float vh = bhv;
            vh = fmaf(Wh[0], mm6[i], vh); vh = fmaf(Wh[1], mm6[i+1], vh); vh = fmaf(Wh[2], mm6[i+2], vh);
            vh = fmaf(Wh[3], cc6[i], vh); vh = fmaf(Wh[4], cc6[i+1], vh); vh = fmaf(Wh[5], cc6[i+2], vh);
            vh = fmaf(Wh[6], pp6[i], vh); vh = fmaf(Wh[7], pp6[i+1], vh); vh = fmaf(Wh[8], pp6[i+2], vh);

            float vw = bwv;
            vw = fmaf(Wv[0], mhm[i], vw);   vw = fmaf(Wv[1], mm6[i+1], vw); vw = fmaf(Wv[2], mhp[i], vw);
            vw = fmaf(Wv[3], cm[i+1], vw);  vw = fmaf(Wv[4], cc6[i+1], vw); vw = fmaf(Wv[5], cp[i+1], vw);
            vw = fmaf(Wv[6], phm[i], vw);   vw = fmaf(Wv[7], pp6[i+1], vw); vw = fmaf(Wv[8], php[i], vw);

            rd[i] = vd; rh[i] = vh; rw[i] = vw;
            s0 += vd; q0 = fmaf(vd, vd, q0);
            s1 += vh; q1 = fmaf(vh, vh, q1);
            s2 += vw; q2 = fmaf(vw, vw, q2);
        }

        const int idx = h * W_ + w4;
        __half2 a0 = __floats2half2_rn(rd[0], rd[1]);
        __half2 a1 = __floats2half2_rn(rd[2], rd[3]);
        __half2 b0 = __floats2half2_rn(rh[0], rh[1]);
        __half2 b1 = __floats2half2_rn(rh[2], rh[3]);
        __half2 c0 = __floats2half2_rn(rw[0], rw[1]);
        __half2 c1 = __floats2half2_rn(rw[2], rw[3]);
        *reinterpret_cast<uint2*>(od + idx) =
            make_uint2(*reinterpret_cast<unsigned*>(&a0), *reinterpret_cast<unsigned*>(&a1));
        *reinterpret_cast<uint2*>(oh + idx) =
            make_uint2(*reinterpret_cast<unsigned*>(&b0), *reinterpret_cast<unsigned*>(&b1));
        *reinterpret_cast<uint2*>(ow + idx) =
            make_uint2(*reinterpret_cast<unsigned*>(&c0), *reinterpret_cast<unsigned*>(&c1));
    }

    s0 = warp_red(s0); q0 = warp_red(q0);
    s1 = warp_red(s1); q1 = warp_red(q1);
    s2 = warp_red(s2); q2 = warp_red(q2);
    if ((threadIdx.x & 31) == 0) {
        atomicAdd(&g_sum[c], s0);             atomicAdd(&g_sq[c], q0);
        atomicAdd(&g_sum[DIMC + c], s1);      atomicAdd(&g_sq[DIMC + c], q1);
        atomicAdd(&g_sum[2 * DIMC + c], s2);  atomicAdd(&g_sq[2 * DIMC + c], q2);
    }
}

__global__ void k_stats() {
    int k = threadIdx.x;
    if (k >= KTOT) return;
    const float n = (float)NSP;
    float mean = g_sum[k] / n;
    float var = g_sq[k] / n - mean * mean;
    float sc = rsqrtf(var + EPS_);
    g_scale[k] = sc;
    g_bias[k] = -mean * sc;
}

// ---------- mma.sync pointwise GEMM ----------
// CTA: 256 threads (8 warps), M=128 positions, N=64, K=192.
// Each warp owns one m16 tile. fp16 pre-norm output; fused output stats.
constexpr int PW_SM_B = 0;                       // 192 * 144 = 27648
constexpr int PW_SM_A = 27648;                   // 192 * 272 = 52224
constexpr int PW_SM_SB = 27648 + 52224;          // 192 float2 = 1536
constexpr int PW_SM_RED = PW_SM_SB + 1536;       // 128 floats = 512
constexpr int PW_SM_TOTAL = PW_SM_RED + 512;     // 81920
constexpr int A_STRIDE = 272;
constexpr int B_STRIDE = 144;

__global__ void __launch_bounds__(256) k_pw_mma() {
    extern __shared__ char smem[];
    const uint32_t sa = smem_to_u32(smem);
    const int tid = threadIdx.x;
    const int wid = tid >> 5;
    const int lid = tid & 31;
    const size_t base = (size_t)blockIdx.x * 128;

    // B: 192 rows x 128B into padded rows
    {
        const uint4* src = reinterpret_cast<const uint4*>(g_wh);
        for (int i = tid; i < KTOT * 8; i += 256) {
            int row = i >> 3, part = i & 7;
            *reinterpret_cast<uint4*>(smem + PW_SM_B + row * B_STRIDE + part * 16) = src[i];
        }
    }
    float2* sbp = reinterpret_cast<float2*>(smem + PW_SM_SB);
    for (int k = tid; k < KTOT; k += 256) sbp[k] = make_float2(g_scale[k], g_bias[k]);
    if (tid < 128) reinterpret_cast<float*>(smem + PW_SM_RED)[tid] = 0.f;
    __syncthreads();

    // A fill: 12 iterations per thread
    #pragma unroll
    for (int it = 0; it < 12; it++) {
        const int idx = it * 256 + tid;
        const int g = idx & 15;
        const int k = idx >> 4;
        uint4 raw = *reinterpret_cast<const uint4*>(g_scrh + (size_t)k * NSP + base + g * 8);
        float2 s = sbp[k];
        const __half2* hp = reinterpret_cast<const __half2*>(&raw);
        uint4 outv;
        uint32_t* ov = reinterpret_cast<uint32_t*>(&outv);
        #pragma unroll
        for (int q = 0; q < 4; q++) {
            float2 f = __half22float2(hp[q]);
            float v0 = fmaf(f.x, s.x, s.y); v0 = fmaxf(v0, SLOPE_ * v0);
            float v1 = fmaf(f.y, s.x, s.y); v1 = fmaxf(v1, SLOPE_ * v1);
            __half2 h = __floats2half2_rn(v0, v1);
            ov[q] = *reinterpret_cast<uint32_t*>(&h);
        }
        *reinterpret_cast<uint4*>(smem + PW_SM_A + k * A_STRIDE + g * 16) = outv;
    }
    __syncthreads();

    // MMA mainloop: warp owns 16 positions (1 m16 tile) x 64 n (8 n8 tiles)
    float acc[8][4];
    #pragma unroll
    for (int nt = 0; nt < 8; nt++)
        #pragma unroll
        for (int e = 0; e < 4; e++) acc[nt][e] = 0.f;

    const int a_k = (lid & 7) | ((lid & 16) >> 1);
    const int a_m = (lid & 8);
    const int b_k = lid & 15;
    const int b_n = (lid >> 4) * 8;
    const int m0 = wid * 16;

    #pragma unroll
    for (int ks = 0; ks < 12; ks++) {
        const int k0 = ks * 16;
        uint32_t af[4];
        ldmx4t(af, sa + PW_SM_A + (k0 + a_k) * A_STRIDE + (m0 + a_m) * 2);
        uint32_t bf[4][4];
        #pragma unroll
        for (int nb = 0; nb < 4; nb++)
            ldmx4t(bf[nb], sa + PW_SM_B + (k0 + b_k) * B_STRIDE + (nb * 16 + b_n) * 2);
        #pragma unroll
        for (int nb = 0; nb < 4; nb++) {
            mma16816(acc[2 * nb],     af, bf[nb][0], bf[nb][1]);
            mma16816(acc[2 * nb + 1], af, bf[nb][2], bf[nb][3]);
        }
    }

    // Epilogue: fp16 store + fused channel stats
    const int r_lo = (lid >> 2);
    const int c_off = (lid & 3) * 2;
    float sc0[8], qc0[8], sc1[8], qc1[8];
    #pragma unroll
    for (int nt = 0; nt < 8; nt++) { sc0[nt] = qc0[nt] = sc1[nt] = qc1[nt] = 0.f; }

    const size_t row0 = base + m0 + r_lo;
    #pragma unroll
    for (int nt = 0; nt < 8; nt++) {
        const int c0 = nt * 8 + c_off;
        float d0 = acc[nt][0], d1 = acc[nt][1];
        float d2 = acc[nt][2], d3 = acc[nt][3];
        g_outh[(size_t)c0 * NSP + row0]           = __float2half(d0);
        g_outh[(size_t)(c0 + 1) * NSP + row0]     = __float2half(d1);
        g_outh[(size_t)c0 * NSP + row0 + 8]       = __float2half(d2);
        g_outh[(size_t)(c0 + 1) * NSP + row0 + 8] = __float2half(d3);
        sc0[nt] += d0 + d2; qc0[nt] += d0 * d0 + d2 * d2;
        sc1[nt] += d1 + d3; qc1[nt] += d1 * d1 + d3 * d3;
    }
    #pragma unroll
    for (int o = 4; o <= 16; o <<= 1) {
        #pragma unroll
        for (int nt = 0; nt < 8; nt++) {
            sc0[nt] += __shfl_xor_sync(0xffffffffu, sc0[nt], o);
            qc0[nt] += __shfl_xor_sync(0xffffffffu, qc0[nt], o);
            sc1[nt] += __shfl_xor_sync(0xffffffffu, sc1[nt], o);
            qc1[nt] += __shfl_xor_sync(0xffffffffu, qc1[nt], o);
        }
    }
    float* red = reinterpret_cast<float*>(smem + PW_SM_RED);
    if (lid < 4) {
        #pragma unroll
        for (int nt = 0; nt < 8; nt++) {
            const int c0 = nt * 8 + c_off;
            atomicAdd(&red[c0], sc0[nt]);
            atomicAdd(&red[64 + c0], qc0[nt]);
            atomicAdd(&red[c0 + 1], sc1[nt]);
            atomicAdd(&red[64 + c0 + 1], qc1[nt]);
        }
    }
    __syncthreads();
    if (tid < 64) atomicAdd(&g_osum[tid], red[tid]);
    else if (tid < 128) atomicAdd(&g_osq[tid - 64], red[tid]);
}

__global__ void k_ofin() {
    int c = threadIdx.x;
    if (c >= DIMC) return;
    const float n = (float)NSP;
    float mean = g_osum[c] / n;
    float var = g_osq[c] / n - mean * mean;
    float sc = rsqrtf(var + EPS_);
    g_oscale[c] = sc;
    g_obias[c] = -mean * sc;
}

// fp16 pre-norm -> normalized fp32 output
__global__ void __launch_bounds__(256) k_onorm(float* __restrict__ out) {
    const int c = blockIdx.y;
    const size_t pos = ((size_t)blockIdx.x * 256 + threadIdx.x) * 8;
    uint4 raw = *reinterpret_cast<const uint4*>(g_outh + (size_t)c * NSP + pos);
    const float sc = g_oscale[c], bi = g_obias[c];
    const __half2* hp = reinterpret_cast<const __half2*>(&raw);
    float o[8];  // contiguous local array (fixes the o0/o1 UB bug)
    #pragma unroll
    for (int q = 0; q < 4; q++) {
        float2 f = __half22float2(hp[q]);
        float v0 = fmaf(f.x, sc, bi); v0 = fmaxf(v0, SLOPE_ * v0);
        float v1 = fmaf(f.y, sc, bi); v1 = fmaxf(v1, SLOPE_ * v1);
        o[2 * q] = v0; o[2 * q + 1] = v1;
    }
    float4* dst = reinterpret_cast<float4*>(out + (size_t)c * NSP + pos);
    dst[0] = make_float4(o[0], o[1], o[2], o[3]);
    dst[1] = make_float4(o[4], o[5], o[6], o[7]);
}

extern "C" void kernel_launch(void* const* d_in, const int* in_sizes, int n_in,
                              void* d_out, int out_size) {
    const float* x   = (const float*)d_in[0];
    const float* wd  = (const float*)d_in[1];
    const float* bd  = (const float*)d_in[2];
    const float* wh  = (const float*)d_in[3];
    const float* bh  = (const float*)d_in[4];
    const float* wv  = (const float*)d_in[5];
    const float* bw  = (const float*)d_in[6];
    const float* wpw = (const float*)d_in[7];
    // d_in[8] = pointwise bias: dropped (cancels exactly in the output InstanceNorm)
    float* out = (float*)d_out;

    cudaFuncSetAttribute(k_pw_mma, cudaFuncAttributeMaxDynamicSharedMemorySize, PW_SM_TOTAL);

    k_prep<<<1, 256>>>(wpw);
    k_conv<<<dim3(D_, DIMC), 256>>>(x, wd, bd, wh, bh, wv, bw);
    k_stats<<<1, KTOT>>>();
    k_pw_mma<<<(unsigned)(NSP / 128), 256, PW_SM_TOTAL>>>();
    k_ofin<<<1, DIMC>>>();
    k_onorm<<<dim3((unsigned)(NSP / 2048), DIMC), 256>>>(out);
}